// round 4
// baseline (speedup 1.0000x reference)
#include <cuda_runtime.h>
#include <stdint.h>

#define KBITS 11
#define KSIZE 2048
#define NPOINTS 262144
#define NCB 8
#define NT 10
#define JOINT_BINS (KSIZE * KSIZE)        /* 4194304 */
#define EPSF 1e-10f

// 10 * 4.19M uint32 = 160 MB scratch. Zero-initialized at module load;
// the entropy kernel restores zeros for every bin it found nonzero, so the
// array is all-zero again at the end of every kernel_launch (deterministic,
// graph-replay safe).
__device__ unsigned int g_joint[(size_t)NT * JOINT_BINS];
__device__ unsigned int g_marg[NCB * KSIZE];
__device__ float        g_Hj[NT];

// Scatter kernel: one pass over the input.
//  - per-block smem histogram for the 8 per-column marginals (64 KB)
//  - per-thread smem staging (stride 9 -> conflict-free) so the dynamic
//    index v[tuple_dim] is an LDS, not a local-memory spill
//  - 10 global REDs per point into the joint histograms
#define STAGE_STRIDE 9
#define SMEM_SCATTER ((NCB * KSIZE + 256 * STAGE_STRIDE) * 4)

__global__ void scatter_kernel(const int* __restrict__ inputs,
                               const int* __restrict__ tdims) {
    extern __shared__ unsigned int sh[];
    unsigned int* s_marg = sh;                      // NCB*KSIZE words
    int* s_val = (int*)(sh + NCB * KSIZE);          // 256*9 words
    __shared__ int s_d0[NT], s_d1[NT];

    const int tid = threadIdx.x;
    for (int i = tid; i < NCB * KSIZE; i += blockDim.x) s_marg[i] = 0;
    if (tid < NT) { s_d0[tid] = tdims[2 * tid]; s_d1[tid] = tdims[2 * tid + 1]; }
    __syncthreads();

    int d0r[NT], d1r[NT];
#pragma unroll
    for (int t = 0; t < NT; t++) { d0r[t] = s_d0[t]; d1r[t] = s_d1[t]; }

    int* my = s_val + tid * STAGE_STRIDE;
    const int stride = gridDim.x * blockDim.x;
    for (int p = blockIdx.x * blockDim.x + tid; p < NPOINTS; p += stride) {
        int4 a = __ldg((const int4*)inputs + 2 * p);
        int4 b = __ldg((const int4*)inputs + 2 * p + 1);
        my[0] = a.x; my[1] = a.y; my[2] = a.z; my[3] = a.w;
        my[4] = b.x; my[5] = b.y; my[6] = b.z; my[7] = b.w;

        atomicAdd(&s_marg[0 * KSIZE + a.x], 1u);
        atomicAdd(&s_marg[1 * KSIZE + a.y], 1u);
        atomicAdd(&s_marg[2 * KSIZE + a.z], 1u);
        atomicAdd(&s_marg[3 * KSIZE + a.w], 1u);
        atomicAdd(&s_marg[4 * KSIZE + b.x], 1u);
        atomicAdd(&s_marg[5 * KSIZE + b.y], 1u);
        atomicAdd(&s_marg[6 * KSIZE + b.z], 1u);
        atomicAdd(&s_marg[7 * KSIZE + b.w], 1u);

#pragma unroll
        for (int t = 0; t < NT; t++) {
            unsigned int key = ((unsigned)my[d0r[t]] << KBITS) | (unsigned)my[d1r[t]];
            atomicAdd(&g_joint[(size_t)t * JOINT_BINS + key], 1u);
        }
    }
    __syncthreads();
    for (int i = tid; i < NCB * KSIZE; i += blockDim.x) {
        unsigned int c = s_marg[i];
        if (c) atomicAdd(&g_marg[i], c);
    }
}

__device__ __forceinline__ float block_reduce_sum(float v) {
#pragma unroll
    for (int o = 16; o; o >>= 1) v += __shfl_down_sync(0xffffffffu, v, o);
    __shared__ float ws[8];
    const int w = threadIdx.x >> 5, l = threadIdx.x & 31;
    if (l == 0) ws[w] = v;
    __syncthreads();
    if (w == 0) {
        v = (l < (int)(blockDim.x >> 5)) ? ws[l] : 0.0f;
#pragma unroll
        for (int o = 4; o; o >>= 1) v += __shfl_down_sync(0xffffffffu, v, o);
    }
    return v;  // valid in thread 0
}

// Entropy over the joint histograms. Reads all 10*4.19M bins, accumulates
// sum(p*log2(p+eps)) for nonzero bins, and restores zeros in-place for any
// uint4 group that had a nonzero bin (replaces a 160 MB memset).
__global__ void joint_entropy_kernel() {
    const int t = blockIdx.y;
    uint4* ptr = reinterpret_cast<uint4*>(g_joint + (size_t)t * JOINT_BINS);
    const int n4 = JOINT_BINS / 4;
    const float invP = 1.0f / (float)NPOINTS;
    float acc = 0.0f;
    const int stride = gridDim.x * blockDim.x;
    for (int i = blockIdx.x * blockDim.x + threadIdx.x; i < n4; i += stride) {
        uint4 c = ptr[i];
        if (c.x | c.y | c.z | c.w) {
            if (c.x) { float p = (float)c.x * invP; acc += p * __log2f(p + EPSF); }
            if (c.y) { float p = (float)c.y * invP; acc += p * __log2f(p + EPSF); }
            if (c.z) { float p = (float)c.z * invP; acc += p * __log2f(p + EPSF); }
            if (c.w) { float p = (float)c.w * invP; acc += p * __log2f(p + EPSF); }
            ptr[i] = make_uint4(0u, 0u, 0u, 0u);
        }
    }
    float total = block_reduce_sum(acc);
    if (threadIdx.x == 0) atomicAdd(&g_Hj[t], total);  // stores -H_joint
}

// One block: per-column marginal entropies (warp w handles column w),
// then combine into the three scalar outputs.
__global__ void finalize_kernel(const int* __restrict__ tdims,
                                float* __restrict__ out) {
    __shared__ float s_Hm[NCB];
    const int w = threadIdx.x >> 5, l = threadIdx.x & 31;
    const float invP = 1.0f / (float)NPOINTS;
    float acc = 0.0f;
    for (int i = l; i < KSIZE; i += 32) {
        unsigned int c = g_marg[w * KSIZE + i];
        if (c) { float p = (float)c * invP; acc += p * __log2f(p + EPSF); }
    }
#pragma unroll
    for (int o = 16; o; o >>= 1) acc += __shfl_down_sync(0xffffffffu, acc, o);
    if (l == 0) s_Hm[w] = -acc;
    __syncthreads();
    if (threadIdx.x == 0) {
        float smi = 0.0f, sHm = 0.0f, sHj = 0.0f;
        for (int t = 0; t < NT; t++) {
            float Hm = s_Hm[tdims[2 * t]] + s_Hm[tdims[2 * t + 1]];
            float Hj = -g_Hj[t];
            smi += (Hm - Hj) / Hm;
            sHm += Hm;
            sHj += Hj;
        }
        out[0] = smi / (float)NT;
        out[1] = sHm / (float)NT;
        out[2] = sHj / (float)NT;
    }
}

extern "C" void kernel_launch(void* const* d_in, const int* in_sizes, int n_in,
                              void* d_out, int out_size) {
    (void)in_sizes; (void)n_in; (void)out_size;
    const int* inputs = (const int*)d_in[0];
    const int* tdims  = (const int*)d_in[1];
    float* out = (float*)d_out;

    cudaFuncSetAttribute(scatter_kernel,
                         cudaFuncAttributeMaxDynamicSharedMemorySize,
                         SMEM_SCATTER);

    void* pm = nullptr; cudaGetSymbolAddress(&pm, g_marg);
    void* ph = nullptr; cudaGetSymbolAddress(&ph, g_Hj);
    cudaMemsetAsync(pm, 0, (size_t)NCB * KSIZE * sizeof(unsigned int));
    cudaMemsetAsync(ph, 0, (size_t)NT * sizeof(float));

    scatter_kernel<<<512, 256, SMEM_SCATTER>>>(inputs, tdims);

    dim3 ge(512, NT);
    joint_entropy_kernel<<<ge, 256>>>();

    finalize_kernel<<<1, 256>>>(tdims, out);
}

// round 8
// speedup vs baseline: 1.0345x; 1.0345x over previous
#include <cuda_runtime.h>
#include <stdint.h>

#define KBITS 11
#define KSIZE 2048
#define NPOINTS 262144
#define NCB 8
#define NT 10
#define NBUCKET 1024          /* low 10 bits of 22-bit key */
#define NBIN 4096             /* bins per bucket = high 12 bits */
#define MAXB 512              /* bucket capacity (avg 256, 16σ margin) */
#define CPAD 8                /* counter padding: 1 counter / 32B sector */
#define BPB 4                 /* buckets per entropy block */
#define EPSF 1e-10f

// Scratch (static => zero at module load; pass B restores counters to zero,
// g_part fully overwritten, stale g_store entries beyond count are ignored).
__device__ unsigned short g_store[(size_t)NT * NBUCKET * MAXB];   // 10 MB
__device__ unsigned int   g_bcnt[NT * NBUCKET * CPAD];            // 320 KB
__device__ float          g_part[NT * NBUCKET];                   // 40 KB
__device__ unsigned int   g_marg[NCB * KSIZE];                    // 64 KB

// ---------------------------------------------------------------------------
// Pass A: one sweep of the input. Marginal counts via direct REDG (no-return,
// fire-and-forget). Joint keys partitioned into per-(tuple,bucket) segments
// of the u16 store via atomicAdd'd cursors. Per-thread smem staging (stride 9,
// conflict-free) keeps the dynamic column select as an LDS, not a spill.
// ---------------------------------------------------------------------------
__global__ __launch_bounds__(256) void partition_kernel(
        const int* __restrict__ inputs, const int* __restrict__ tdims) {
    __shared__ int s_val[256 * 9];
    __shared__ int s_d0[NT], s_d1[NT];
    const int tid = threadIdx.x;
    if (tid < NT) { s_d0[tid] = tdims[2 * tid]; s_d1[tid] = tdims[2 * tid + 1]; }
    __syncthreads();

    int d0r[NT], d1r[NT];
#pragma unroll
    for (int t = 0; t < NT; t++) { d0r[t] = s_d0[t]; d1r[t] = s_d1[t]; }

    int* my = s_val + tid * 9;
    const int stride = gridDim.x * blockDim.x;
    for (int p = blockIdx.x * blockDim.x + tid; p < NPOINTS; p += stride) {
        int4 a = __ldg((const int4*)inputs + 2 * p);
        int4 b = __ldg((const int4*)inputs + 2 * p + 1);
        my[0] = a.x; my[1] = a.y; my[2] = a.z; my[3] = a.w;
        my[4] = b.x; my[5] = b.y; my[6] = b.z; my[7] = b.w;

        atomicAdd(&g_marg[0 * KSIZE + a.x], 1u);
        atomicAdd(&g_marg[1 * KSIZE + a.y], 1u);
        atomicAdd(&g_marg[2 * KSIZE + a.z], 1u);
        atomicAdd(&g_marg[3 * KSIZE + a.w], 1u);
        atomicAdd(&g_marg[4 * KSIZE + b.x], 1u);
        atomicAdd(&g_marg[5 * KSIZE + b.y], 1u);
        atomicAdd(&g_marg[6 * KSIZE + b.z], 1u);
        atomicAdd(&g_marg[7 * KSIZE + b.w], 1u);

#pragma unroll
        for (int t = 0; t < NT; t++) {
            unsigned key = ((unsigned)my[d0r[t]] << KBITS) | (unsigned)my[d1r[t]];
            unsigned bucket = key & (NBUCKET - 1);
            unsigned inner  = key >> 10;              // 12 bits
            unsigned idx    = t * NBUCKET + bucket;
            unsigned pos = atomicAdd(&g_bcnt[idx * CPAD], 1u);
            if (pos < MAXB)
                g_store[(size_t)idx * MAXB + pos] = (unsigned short)inner;
        }
    }
}

// ---------------------------------------------------------------------------
// Pass B: per (tuple, bucket) smem histogram (4096 bins) + entropy over the
// nonzero bins. Also resets the bucket counter (keeps replay deterministic).
// ---------------------------------------------------------------------------
__global__ __launch_bounds__(256) void bucket_entropy_kernel() {
    __shared__ unsigned int hist[NBIN];     // 16 KB
    __shared__ float ws[8];
    const int t = blockIdx.y;
    const int tid = threadIdx.x;
    const int w = tid >> 5, l = tid & 31;
    uint4* h4 = (uint4*)hist;
    const float invP = 1.0f / (float)NPOINTS;

#pragma unroll 1
    for (int g = 0; g < BPB; g++) {
        const int bucket = blockIdx.x * BPB + g;
        const unsigned idx = t * NBUCKET + bucket;

        for (int i = tid; i < NBIN / 4; i += 256)
            h4[i] = make_uint4(0u, 0u, 0u, 0u);
        __syncthreads();

        unsigned c = g_bcnt[idx * CPAD];
        if (c > MAXB) c = MAXB;
        const unsigned short* keys = g_store + (size_t)idx * MAXB;
        for (unsigned i = tid; i < c; i += 256)
            atomicAdd(&hist[keys[i]], 1u);
        __syncthreads();

        float acc = 0.0f;
        for (int i = tid; i < NBIN / 4; i += 256) {
            uint4 v = h4[i];
            if (v.x | v.y | v.z | v.w) {
                if (v.x) { float p = (float)v.x * invP; acc += p * __log2f(p + EPSF); }
                if (v.y) { float p = (float)v.y * invP; acc += p * __log2f(p + EPSF); }
                if (v.z) { float p = (float)v.z * invP; acc += p * __log2f(p + EPSF); }
                if (v.w) { float p = (float)v.w * invP; acc += p * __log2f(p + EPSF); }
            }
        }
#pragma unroll
        for (int o = 16; o; o >>= 1) acc += __shfl_down_sync(0xffffffffu, acc, o);
        if (l == 0) ws[w] = acc;
        __syncthreads();
        if (tid == 0) {
            float s = 0.0f;
#pragma unroll
            for (int i = 0; i < 8; i++) s += ws[i];
            g_part[idx] = s;                 // holds sum p*log2(p+eps) = -H contribution
            g_bcnt[idx * CPAD] = 0u;         // restore for next replay
        }
        __syncthreads();
    }
}

// ---------------------------------------------------------------------------
// Finalize: per-column marginal entropies (warp per column), per-tuple joint
// entropy from partials, then the three scalar outputs.
// ---------------------------------------------------------------------------
__global__ __launch_bounds__(256) void finalize_kernel(
        const int* __restrict__ tdims, float* __restrict__ out) {
    __shared__ float s_Hm[NCB];
    __shared__ float s_Hj[NT];
    __shared__ float ws[8];
    const int tid = threadIdx.x;
    const int w = tid >> 5, l = tid & 31;
    const float invP = 1.0f / (float)NPOINTS;

    // marginal entropy of column w (warps 0..7)
    {
        float acc = 0.0f;
        for (int i = l; i < KSIZE; i += 32) {
            unsigned c = g_marg[w * KSIZE + i];
            if (c) { float p = (float)c * invP; acc += p * __log2f(p + EPSF); }
        }
#pragma unroll
        for (int o = 16; o; o >>= 1) acc += __shfl_down_sync(0xffffffffu, acc, o);
        if (l == 0) s_Hm[w] = -acc;
    }
    __syncthreads();

    // joint entropies
    for (int t = 0; t < NT; t++) {
        float acc = 0.0f;
        for (int i = tid; i < NBUCKET; i += 256) acc += g_part[t * NBUCKET + i];
#pragma unroll
        for (int o = 16; o; o >>= 1) acc += __shfl_down_sync(0xffffffffu, acc, o);
        if (l == 0) ws[w] = acc;
        __syncthreads();
        if (tid == 0) {
            float s = 0.0f;
#pragma unroll
            for (int i = 0; i < 8; i++) s += ws[i];
            s_Hj[t] = -s;
        }
        __syncthreads();
    }

    if (tid == 0) {
        float smi = 0.0f, sHm = 0.0f, sHj = 0.0f;
        for (int t = 0; t < NT; t++) {
            float Hm = s_Hm[tdims[2 * t]] + s_Hm[tdims[2 * t + 1]];
            float Hj = s_Hj[t];
            smi += (Hm - Hj) / Hm;
            sHm += Hm;
            sHj += Hj;
        }
        out[0] = smi / (float)NT;
        out[1] = sHm / (float)NT;
        out[2] = sHj / (float)NT;
    }
}

extern "C" void kernel_launch(void* const* d_in, const int* in_sizes, int n_in,
                              void* d_out, int out_size) {
    (void)in_sizes; (void)n_in; (void)out_size;
    const int* inputs = (const int*)d_in[0];
    const int* tdims  = (const int*)d_in[1];
    float* out = (float*)d_out;

    void* pm = nullptr; cudaGetSymbolAddress(&pm, g_marg);
    cudaMemsetAsync(pm, 0, (size_t)NCB * KSIZE * sizeof(unsigned int));

    partition_kernel<<<1024, 256>>>(inputs, tdims);

    dim3 ge(NBUCKET / BPB, NT);
    bucket_entropy_kernel<<<ge, 256>>>();

    finalize_kernel<<<1, 256>>>(tdims, out);
}

// round 11
// speedup vs baseline: 1.1913x; 1.1516x over previous
#include <cuda_runtime.h>
#include <stdint.h>

#define KBITS 11
#define KSIZE 2048
#define NPOINTS 262144
#define NCB 8
#define NT 10
#define NBUCKET 1024          /* low 10 bits of 22-bit key */
#define NBIN 4096             /* bins per bucket = high 12 bits */
#define SHARDS 4              /* cursor shards per bucket (by warp&3) */
#define MAXB_SH 192           /* capacity per shard (avg 64, huge margin) */
#define CPAD 8                /* counter padding: 1 counter / 32B sector */
#define BPB 4                 /* buckets per entropy block */
#define LUT_N 769             /* max possible bin count = 4*192 + 1 */
#define EPSF 1e-10f

// Static scratch: zero at module load; every launch restores it to zero
// (counters reset in pass B, g_marg reset in finalize, g_part overwritten,
// stale g_store beyond counts ignored) -> graph-replay deterministic.
__device__ unsigned short g_store[(size_t)NT * NBUCKET * SHARDS * MAXB_SH]; // 15.7 MB
__device__ unsigned int   g_bcnt[NT * NBUCKET * SHARDS * CPAD];             // 1.3 MB
__device__ float          g_part[NT * NBUCKET];
__device__ unsigned int   g_marg[NCB * KSIZE];

// ---------------------------------------------------------------------------
// Pass A: one point per thread. Marginal REDs with per-thread rotated column
// order; joint keys partitioned into (tuple,bucket,shard) segments with
// per-warp rotated tuple order. Rotation + sharding de-phase the atomic
// waves that made the previous version contention-latency bound.
// ---------------------------------------------------------------------------
__global__ __launch_bounds__(256) void partition_kernel(
        const int* __restrict__ inputs, const int* __restrict__ tdims) {
    __shared__ int s_val[256 * 9];
    __shared__ int s_d0[NT], s_d1[NT];
    const int tid = threadIdx.x;
    if (tid < NT) { s_d0[tid] = tdims[2 * tid]; s_d1[tid] = tdims[2 * tid + 1]; }
    __syncthreads();

    const int warp_g = blockIdx.x * 8 + (tid >> 5);
    const int t0 = warp_g % NT;
    const unsigned shard = (unsigned)(tid >> 5) & (SHARDS - 1);

    int d0r[NT], d1r[NT];
    unsigned cb[NT];
#pragma unroll
    for (int j = 0; j < NT; j++) {
        int t = t0 + j; if (t >= NT) t -= NT;
        d0r[j] = s_d0[t];
        d1r[j] = s_d1[t];
        cb[j] = (unsigned)t * NBUCKET;
    }

    int* my = s_val + tid * 9;
    const int p = blockIdx.x * 256 + tid;           // grid = 1024 blocks exactly
    int4 a = __ldg((const int4*)inputs + 2 * p);
    int4 b = __ldg((const int4*)inputs + 2 * p + 1);
    my[0] = a.x; my[1] = a.y; my[2] = a.z; my[3] = a.w;
    my[4] = b.x; my[5] = b.y; my[6] = b.z; my[7] = b.w;

    // marginal histogram REDs, column order rotated per thread
    const int c0 = tid & 7;
#pragma unroll
    for (int j = 0; j < NCB; j++) {
        int c = (c0 + j) & 7;
        atomicAdd(&g_marg[c * KSIZE + my[c]], 1u);
    }

    // joint-key partitioning, tuple order rotated per warp, sharded cursors
#pragma unroll
    for (int j = 0; j < NT; j++) {
        unsigned key = ((unsigned)my[d0r[j]] << KBITS) | (unsigned)my[d1r[j]];
        unsigned bucket = key & (NBUCKET - 1);
        unsigned inner  = key >> 10;                // 12 bits
        unsigned cidx   = (cb[j] + bucket) * SHARDS + shard;
        unsigned pos = atomicAdd(&g_bcnt[cidx * CPAD], 1u);
        if (pos < MAXB_SH)
            g_store[(size_t)cidx * MAXB_SH + pos] = (unsigned short)inner;
    }
}

// ---------------------------------------------------------------------------
// Pass B: O(items) entropy. Per bucket: count items into a shared hist
// (zeroed ONCE per block, restored per-item afterward), then each item adds
// lut[hist[key]] where lut[c] = (c/N)*log2(c/N + eps)/c, so a bin of count c
// contributes exactly p*log2(p+eps). No 4096-bin sweep anywhere.
// ---------------------------------------------------------------------------
__global__ __launch_bounds__(256) void bucket_entropy_kernel() {
    __shared__ unsigned int hist[NBIN];      // 16 KB, zeroed once per block
    __shared__ float lut[LUT_N];
    __shared__ float ws[8];
    const int t = blockIdx.y;
    const int tid = threadIdx.x;
    const int w = tid >> 5, l = tid & 31;
    const float invP = 1.0f / (float)NPOINTS;

    uint4* h4 = (uint4*)hist;
    for (int i = tid; i < NBIN / 4; i += 256) h4[i] = make_uint4(0u, 0u, 0u, 0u);
    for (int c = tid; c < LUT_N; c += 256) {
        if (c == 0) lut[0] = 0.0f;
        else {
            float p = (float)c * invP;
            lut[c] = p * __log2f(p + EPSF) / (float)c;
        }
    }
    __syncthreads();

#pragma unroll 1
    for (int g = 0; g < BPB; g++) {
        const int bucket = blockIdx.x * BPB + g;
        const unsigned idx = (unsigned)t * NBUCKET + bucket;

        // phase 1: load my items (<=1 per thread per shard) + count
        unsigned short mykey[SHARDS];
        int have[SHARDS];
#pragma unroll
        for (int s = 0; s < SHARDS; s++) {
            unsigned c = g_bcnt[(idx * SHARDS + s) * CPAD];
            if (c > MAXB_SH) c = MAXB_SH;
            have[s] = (tid < (int)c);
            if (have[s]) {
                mykey[s] = g_store[(size_t)(idx * SHARDS + s) * MAXB_SH + tid];
                atomicAdd(&hist[mykey[s]], 1u);
            }
        }
        __syncthreads();

        // phase 2: per-item entropy contribution via LUT
        float acc = 0.0f;
#pragma unroll
        for (int s = 0; s < SHARDS; s++)
            if (have[s]) acc += lut[hist[mykey[s]]];
        __syncthreads();

        // phase 3: restore zeros (per item) + reset counters
#pragma unroll
        for (int s = 0; s < SHARDS; s++)
            if (have[s]) hist[mykey[s]] = 0u;
        if (tid < SHARDS) g_bcnt[(idx * SHARDS + tid) * CPAD] = 0u;

        // block reduce
#pragma unroll
        for (int o = 16; o; o >>= 1) acc += __shfl_down_sync(0xffffffffu, acc, o);
        if (l == 0) ws[w] = acc;
        __syncthreads();
        if (tid == 0) {
            float s = 0.0f;
#pragma unroll
            for (int i = 0; i < 8; i++) s += ws[i];
            g_part[idx] = s;            // sum p*log2(p+eps)  (= -H contribution)
        }
        __syncthreads();
    }
}

// ---------------------------------------------------------------------------
// Finalize: marginal entropies (warp per column; also restores g_marg to 0),
// joint entropies from partials, then the three scalar outputs.
// ---------------------------------------------------------------------------
__global__ __launch_bounds__(256) void finalize_kernel(
        const int* __restrict__ tdims, float* __restrict__ out) {
    __shared__ float s_Hm[NCB];
    __shared__ float s_Hj[NT];
    __shared__ float ws[8];
    const int tid = threadIdx.x;
    const int w = tid >> 5, l = tid & 31;
    const float invP = 1.0f / (float)NPOINTS;

    {
        float acc = 0.0f;
        for (int i = l; i < KSIZE; i += 32) {
            unsigned c = g_marg[w * KSIZE + i];
            g_marg[w * KSIZE + i] = 0u;          // restore for next replay
            if (c) { float p = (float)c * invP; acc += p * __log2f(p + EPSF); }
        }
#pragma unroll
        for (int o = 16; o; o >>= 1) acc += __shfl_down_sync(0xffffffffu, acc, o);
        if (l == 0) s_Hm[w] = -acc;
    }
    __syncthreads();

    for (int t = 0; t < NT; t++) {
        float acc = 0.0f;
        for (int i = tid; i < NBUCKET; i += 256) acc += g_part[t * NBUCKET + i];
#pragma unroll
        for (int o = 16; o; o >>= 1) acc += __shfl_down_sync(0xffffffffu, acc, o);
        if (l == 0) ws[w] = acc;
        __syncthreads();
        if (tid == 0) {
            float s = 0.0f;
#pragma unroll
            for (int i = 0; i < 8; i++) s += ws[i];
            s_Hj[t] = -s;
        }
        __syncthreads();
    }

    if (tid == 0) {
        float smi = 0.0f, sHm = 0.0f, sHj = 0.0f;
        for (int t = 0; t < NT; t++) {
            float Hm = s_Hm[tdims[2 * t]] + s_Hm[tdims[2 * t + 1]];
            float Hj = s_Hj[t];
            smi += (Hm - Hj) / Hm;
            sHm += Hm;
            sHj += Hj;
        }
        out[0] = smi / (float)NT;
        out[1] = sHm / (float)NT;
        out[2] = sHj / (float)NT;
    }
}

extern "C" void kernel_launch(void* const* d_in, const int* in_sizes, int n_in,
                              void* d_out, int out_size) {
    (void)in_sizes; (void)n_in; (void)out_size;
    const int* inputs = (const int*)d_in[0];
    const int* tdims  = (const int*)d_in[1];
    float* out = (float*)d_out;

    partition_kernel<<<1024, 256>>>(inputs, tdims);

    dim3 ge(NBUCKET / BPB, NT);
    bucket_entropy_kernel<<<ge, 256>>>();

    finalize_kernel<<<1, 256>>>(tdims, out);
}

// round 15
// speedup vs baseline: 1.3037x; 1.0943x over previous
#include <cuda_runtime.h>
#include <stdint.h>

#define KBITS 11
#define KSIZE 2048
#define NPOINTS 262144
#define NCB 8
#define NT 10
#define GSIZE 5                               /* tuples per group */
#define NGROUP (NT / GSIZE)
#define JOINT_BINS (KSIZE * KSIZE)            /* 4194304 bins, 16 MB */
#define EGRID 512                             /* entropy grid.x */
#define EPSF 1e-10f

// 5 x 16 MB = 80 MB reused across the two groups; L2-resident during each
// scatter->entropy pair. Static => zero at load; entropy pass restores zeros,
// g_marg restored in finalize, g_partJ fully overwritten => replay-safe.
__device__ unsigned int g_joint[(size_t)GSIZE * JOINT_BINS];   // 80 MB
__device__ unsigned int g_marg[NCB * KSIZE];
__device__ float        g_partJ[NT * EGRID];

// ---------------------------------------------------------------------------
// Scatter for one group of 5 tuples: one point per thread, 5 fire-and-forget
// REDs into the L2-resident joint buffer. Group 0 also accumulates the 8
// per-column marginals (column order rotated per thread to de-phase).
// ---------------------------------------------------------------------------
__global__ __launch_bounds__(256) void scatter_kernel(
        const int* __restrict__ inputs, const int* __restrict__ tdims,
        int t0, int with_marg) {
    __shared__ int s_val[256 * 9];
    __shared__ int s_d0[GSIZE], s_d1[GSIZE];
    const int tid = threadIdx.x;
    if (tid < GSIZE) {
        s_d0[tid] = tdims[2 * (t0 + tid)];
        s_d1[tid] = tdims[2 * (t0 + tid) + 1];
    }
    __syncthreads();

    int d0r[GSIZE], d1r[GSIZE];
#pragma unroll
    for (int j = 0; j < GSIZE; j++) { d0r[j] = s_d0[j]; d1r[j] = s_d1[j]; }

    int* my = s_val + tid * 9;
    const int p = blockIdx.x * 256 + tid;          // grid.x = 1024 exactly
    int4 a = __ldg((const int4*)inputs + 2 * p);
    int4 b = __ldg((const int4*)inputs + 2 * p + 1);
    my[0] = a.x; my[1] = a.y; my[2] = a.z; my[3] = a.w;
    my[4] = b.x; my[5] = b.y; my[6] = b.z; my[7] = b.w;

    if (with_marg) {
        const int c0 = tid & 7;
#pragma unroll
        for (int j = 0; j < NCB; j++) {
            int c = (c0 + j) & 7;
            atomicAdd(&g_marg[c * KSIZE + my[c]], 1u);
        }
    }

#pragma unroll
    for (int j = 0; j < GSIZE; j++) {
        unsigned key = ((unsigned)my[d0r[j]] << KBITS) | (unsigned)my[d1r[j]];
        atomicAdd(&g_joint[(size_t)j * JOINT_BINS + key], 1u);   // RED (no return)
    }
}

__device__ __forceinline__ float block_reduce_sum(float v) {
#pragma unroll
    for (int o = 16; o; o >>= 1) v += __shfl_down_sync(0xffffffffu, v, o);
    __shared__ float ws[8];
    const int w = threadIdx.x >> 5, l = threadIdx.x & 31;
    if (l == 0) ws[w] = v;
    __syncthreads();
    float s = 0.0f;
    if (threadIdx.x == 0) {
#pragma unroll
        for (int i = 0; i < 8; i++) s += ws[i];
    }
    __syncthreads();
    return s;      // valid in thread 0
}

// ---------------------------------------------------------------------------
// Entropy over one group's 5 joint histograms (blockIdx.y = local tuple).
// uint4 sweep of 4M bins (~L2-resident); entropy only on nonzero bins;
// restores zeros for nonzero groups so the buffer ends all-zero. Per-block
// partials to g_partJ -> deterministic final summation order.
// ---------------------------------------------------------------------------
__global__ __launch_bounds__(256) void joint_entropy_kernel(int t0) {
    const int tl = blockIdx.y;
    uint4* ptr = reinterpret_cast<uint4*>(g_joint + (size_t)tl * JOINT_BINS);
    const int n4 = JOINT_BINS / 4;
    const float invP = 1.0f / (float)NPOINTS;
    float acc = 0.0f;
    const int stride = EGRID * 256;
    for (int i = blockIdx.x * 256 + threadIdx.x; i < n4; i += stride) {
        uint4 c = ptr[i];
        if (c.x | c.y | c.z | c.w) {
            if (c.x) { float p = (float)c.x * invP; acc += p * __log2f(p + EPSF); }
            if (c.y) { float p = (float)c.y * invP; acc += p * __log2f(p + EPSF); }
            if (c.z) { float p = (float)c.z * invP; acc += p * __log2f(p + EPSF); }
            if (c.w) { float p = (float)c.w * invP; acc += p * __log2f(p + EPSF); }
            ptr[i] = make_uint4(0u, 0u, 0u, 0u);
        }
    }
    float total = block_reduce_sum(acc);
    if (threadIdx.x == 0)
        g_partJ[(t0 + tl) * EGRID + blockIdx.x] = total;   // sum p*log2(p+eps)
}

// ---------------------------------------------------------------------------
// Finalize: marginal entropies (warp per column, restores g_marg to zero),
// joint entropies from the 512 per-block partials (fixed order), outputs.
// ---------------------------------------------------------------------------
__global__ __launch_bounds__(256) void finalize_kernel(
        const int* __restrict__ tdims, float* __restrict__ out) {
    __shared__ float s_Hm[NCB];
    __shared__ float s_Hj[NT];
    __shared__ float ws[8];
    const int tid = threadIdx.x;
    const int w = tid >> 5, l = tid & 31;
    const float invP = 1.0f / (float)NPOINTS;

    {
        float acc = 0.0f;
        for (int i = l; i < KSIZE; i += 32) {
            unsigned c = g_marg[w * KSIZE + i];
            g_marg[w * KSIZE + i] = 0u;                 // restore for replay
            if (c) { float p = (float)c * invP; acc += p * __log2f(p + EPSF); }
        }
#pragma unroll
        for (int o = 16; o; o >>= 1) acc += __shfl_down_sync(0xffffffffu, acc, o);
        if (l == 0) s_Hm[w] = -acc;
    }
    __syncthreads();

    for (int t = 0; t < NT; t++) {
        float acc = 0.0f;
        for (int i = tid; i < EGRID; i += 256) acc += g_partJ[t * EGRID + i];
#pragma unroll
        for (int o = 16; o; o >>= 1) acc += __shfl_down_sync(0xffffffffu, acc, o);
        if (l == 0) ws[w] = acc;
        __syncthreads();
        if (tid == 0) {
            float s = 0.0f;
#pragma unroll
            for (int i = 0; i < 8; i++) s += ws[i];
            s_Hj[t] = -s;
        }
        __syncthreads();
    }

    if (tid == 0) {
        float smi = 0.0f, sHm = 0.0f, sHj = 0.0f;
        for (int t = 0; t < NT; t++) {
            float Hm = s_Hm[tdims[2 * t]] + s_Hm[tdims[2 * t + 1]];
            float Hj = s_Hj[t];
            smi += (Hm - Hj) / Hm;
            sHm += Hm;
            sHj += Hj;
        }
        out[0] = smi / (float)NT;
        out[1] = sHm / (float)NT;
        out[2] = sHj / (float)NT;
    }
}

extern "C" void kernel_launch(void* const* d_in, const int* in_sizes, int n_in,
                              void* d_out, int out_size) {
    (void)in_sizes; (void)n_in; (void)out_size;
    const int* inputs = (const int*)d_in[0];
    const int* tdims  = (const int*)d_in[1];
    float* out = (float*)d_out;

    dim3 ge(EGRID, GSIZE);
    for (int g = 0; g < NGROUP; g++) {
        scatter_kernel<<<NPOINTS / 256, 256>>>(inputs, tdims, g * GSIZE, g == 0);
        joint_entropy_kernel<<<ge, 256>>>(g * GSIZE);
    }
    finalize_kernel<<<1, 256>>>(tdims, out);
}